// round 16
// baseline (speedup 1.0000x reference)
#include <cuda_runtime.h>
#include <cuda_bf16.h>
#include <cuda_fp16.h>
#include <cstdint>
#include <cstddef>

#define S_DIM 2048
#define E_DIM 1024
#define H_NUM 16
#define DH_DIM 64
#define B_NUM 2
#define BH_NUM (B_NUM * H_NUM)     // 32
#define M_ROWS (B_NUM * S_DIM)     // 4096

// tiled fp16 hi/lo operand images (each tile = 8KB hi plane + 8KB lo plane)
__device__ __align__(16) unsigned char g_A2[(size_t)32 * 32 * 16384];        // features tiled [mb][kc]
__device__ __align__(16) unsigned char g_W2[(size_t)4 * 8 * 32 * 16384];     // 4 weights [w][nb][kc]
__device__ __align__(16) unsigned char g_qkv2[(size_t)3 * 32 * 32 * 16384];  // q/k/v [which][z][t]
__device__ __align__(16) unsigned char g_ctx2[(size_t)32 * 32 * 16384];      // ctx tiled [mb][kc]
__device__ __align__(16) unsigned char g_pt[(size_t)32 * 16 * 8 * 65536];    // p~ fp16 fragment blobs (256MB)
__device__ float g_attn[(size_t)BH_NUM * S_DIM * S_DIM];                     // fallback

// ---------------------------------------------------------------------------
// helpers
// ---------------------------------------------------------------------------
__device__ __forceinline__ uint32_t smem_u32(const void* p) {
    uint32_t a;
    asm("{ .reg .u64 t; cvta.to.shared.u64 t, %1; cvt.u32.u64 %0, t; }" : "=r"(a) : "l"(p));
    return a;
}
__device__ __forceinline__ void ldm4(uint32_t* r, uint32_t a) {
    asm volatile("ldmatrix.sync.aligned.m8n8.x4.shared.b16 {%0,%1,%2,%3}, [%4];"
        : "=r"(r[0]), "=r"(r[1]), "=r"(r[2]), "=r"(r[3]) : "r"(a));
}
__device__ __forceinline__ void ldm4t(uint32_t* r, uint32_t a) {
    asm volatile("ldmatrix.sync.aligned.m8n8.x4.trans.shared.b16 {%0,%1,%2,%3}, [%4];"
        : "=r"(r[0]), "=r"(r[1]), "=r"(r[2]), "=r"(r[3]) : "r"(a));
}
__device__ __forceinline__ void mma_f16(float* c, const uint32_t* a, uint32_t b0, uint32_t b1) {
    asm volatile(
        "mma.sync.aligned.m16n8k16.row.col.f32.f16.f16.f32 "
        "{%0,%1,%2,%3}, {%4,%5,%6,%7}, {%8,%9}, {%0,%1,%2,%3};"
        : "+f"(c[0]), "+f"(c[1]), "+f"(c[2]), "+f"(c[3])
        : "r"(a[0]), "r"(a[1]), "r"(a[2]), "r"(a[3]), "r"(b0), "r"(b1));
}
__device__ __forceinline__ void cpa16(uint32_t s, const void* g) {
    asm volatile("cp.async.cg.shared.global [%0], [%1], 16;" :: "r"(s), "l"(g));
}
#define CPA_COMMIT() asm volatile("cp.async.commit_group;" ::: "memory")
#define CPA_WAIT0()  asm volatile("cp.async.wait_group 0;" ::: "memory")
#define CPA_WAIT1()  asm volatile("cp.async.wait_group 1;" ::: "memory")

__device__ __forceinline__ uint32_t swp128(int row, int c2) { return (uint32_t)(row * 128 + c2) ^ ((row & 7) << 4); }
__device__ __forceinline__ uint32_t swp64 (int row, int c2) { return (uint32_t)(row * 64  + c2) ^ (((row >> 1) & 3) << 4); }
__device__ __forceinline__ uint32_t swp256(int row, int c2) { return (uint32_t)(row * 256 + c2) ^ ((row & 7) << 4); }

__device__ __forceinline__ float ex2f(float x) {
    float y;
    asm("ex2.approx.f32 %0, %1;" : "=f"(y) : "f"(x));
    return y;
}

// fp16 hi/lo split of 8 floats
__device__ __forceinline__ void split8_f16(const float* v, uint32_t* hi, uint32_t* lo) {
#pragma unroll
    for (int q = 0; q < 4; q++) {
        __half h0 = __float2half_rn(v[2*q]);
        __half h1 = __float2half_rn(v[2*q+1]);
        __half l0 = __float2half_rn(v[2*q]   - __half2float(h0));
        __half l1 = __float2half_rn(v[2*q+1] - __half2float(h1));
        hi[q] = (uint32_t)__half_as_ushort(h0) | ((uint32_t)__half_as_ushort(h1) << 16);
        lo[q] = (uint32_t)__half_as_ushort(l0) | ((uint32_t)__half_as_ushort(l1) << 16);
    }
}
__device__ __forceinline__ uint32_t pack_f16(float a, float b, uint32_t& lo) {
    __half ha = __float2half_rn(a), hb = __float2half_rn(b);
    __half la = __float2half_rn(a - __half2float(ha));
    __half lb = __float2half_rn(b - __half2float(hb));
    lo = (uint32_t)__half_as_ushort(la) | ((uint32_t)__half_as_ushort(lb) << 16);
    return (uint32_t)__half_as_ushort(ha) | ((uint32_t)__half_as_ushort(hb) << 16);
}
__device__ __forceinline__ uint32_t pack_f16_hi(float a, float b) {
    __half ha = __float2half_rn(a), hb = __float2half_rn(b);
    return (uint32_t)__half_as_ushort(ha) | ((uint32_t)__half_as_ushort(hb) << 16);
}
// copy one 16KB tile (hi+lo planes) gmem->smem, 256 threads
__device__ __forceinline__ void cp_tile16(uint32_t sdst, const unsigned char* gsrc, int tid) {
#pragma unroll
    for (int i = 0; i < 4; i++)
        cpa16(sdst + tid * 16 + i * 4096, gsrc + tid * 16 + i * 4096);
}
// copy only the 8KB hi plane, 256 threads
__device__ __forceinline__ void cp_tile8(uint32_t sdst, const unsigned char* gsrc, int tid) {
#pragma unroll
    for (int i = 0; i < 2; i++)
        cpa16(sdst + tid * 16 + i * 4096, gsrc + tid * 16 + i * 4096);
}

// ---------------------------------------------------------------------------
// conversion kernels (run once, cheap) — fp16 hi/lo images
// ---------------------------------------------------------------------------
__global__ void __launch_bounds__(256) convA(const float* __restrict__ src,
                                             unsigned char* __restrict__ dst)
{
    int kc = blockIdx.x, mb = blockIdx.y;
    int tid = threadIdx.x;
    int row = tid >> 1, c0 = (tid & 1) * 16;
    const float* p = src + (size_t)(mb * 128 + row) * E_DIM + kc * 32 + c0;
    unsigned char* base = dst + ((size_t)(mb * 32 + kc)) * 16384;
#pragma unroll
    for (int gi = 0; gi < 2; gi++) {
        float v[8];
        *(float4*)(v)     = *(const float4*)(p + gi * 8);
        *(float4*)(v + 4) = *(const float4*)(p + gi * 8 + 4);
        uint32_t hi[4], lo[4];
        split8_f16(v, hi, lo);
        uint32_t sw = swp64(row, (c0 + gi * 8) * 2);
        *(uint4*)(base + sw)        = make_uint4(hi[0], hi[1], hi[2], hi[3]);
        *(uint4*)(base + 8192 + sw) = make_uint4(lo[0], lo[1], lo[2], lo[3]);
    }
}
__global__ void __launch_bounds__(256) convW(
    const float* __restrict__ Wq, const float* __restrict__ Wk,
    const float* __restrict__ Wv, const float* __restrict__ Wo,
    unsigned char* __restrict__ dst)
{
    int kc = blockIdx.x, nb = blockIdx.y, w = blockIdx.z;
    const float* W = w == 0 ? Wq : (w == 1 ? Wk : (w == 2 ? Wv : Wo));
    int tid = threadIdx.x;
    int krow = tid >> 3, nseg = (tid & 7) * 16;
    const float* p = W + (size_t)(kc * 32 + krow) * E_DIM + nb * 128 + nseg;
    unsigned char* base = dst + ((size_t)w * 8 * 32 + (size_t)(nb * 32 + kc)) * 16384;
#pragma unroll
    for (int gi = 0; gi < 2; gi++) {
        float v[8];
        *(float4*)(v)     = *(const float4*)(p + gi * 8);
        *(float4*)(v + 4) = *(const float4*)(p + gi * 8 + 4);
        uint32_t hi[4], lo[4];
        split8_f16(v, hi, lo);
        uint32_t sw = swp256(krow, (nseg + gi * 8) * 2);
        *(uint4*)(base + sw)        = make_uint4(hi[0], hi[1], hi[2], hi[3]);
        *(uint4*)(base + 8192 + sw) = make_uint4(lo[0], lo[1], lo[2], lo[3]);
    }
}

// ---------------------------------------------------------------------------
// Projection GEMM, fp16 2-term: C = (A_hi + A_lo) @ W_hi + bias.
// ---------------------------------------------------------------------------
#define PROJ_SMEM 49152
__global__ void __launch_bounds__(256, 2) proj_mma(
    const unsigned char* __restrict__ A2, const unsigned char* __restrict__ W2,
    const float* __restrict__ b0p, const float* __restrict__ b1p, const float* __restrict__ b2p,
    unsigned char* __restrict__ qkvout, float* __restrict__ fout, int mode)
{
    extern __shared__ char sm[];
    uint32_t sb = smem_u32(sm);
    int zz = blockIdx.z;
    const float* bias = zz == 0 ? b0p : (zz == 1 ? b1p : b2p);
    const unsigned char* Wsel = W2 + (size_t)zz * 8 * 32 * 16384;

    int tid = threadIdx.x, lane = tid & 31, wid = tid >> 5;
    int warp_m = wid & 3, warp_n = wid >> 2;
    int n0 = blockIdx.x * 128, m0 = blockIdx.y * 128;
    int lrow = lane & 7, grp = lane >> 3;
    const unsigned char* Abase = A2 + ((size_t)(m0 >> 7) * 32) * 16384;
    const unsigned char* Wbase = Wsel + ((size_t)(n0 >> 7) * 32) * 16384;

    float acc[16][4] = {};
    cp_tile16(sb, Abase, tid);
    cp_tile8(sb + 16384, Wbase, tid);
    CPA_COMMIT();

    for (int c = 0; c < 32; c++) {
        int cur = (c & 1) * 24576;
        if (c < 31) {
            int nb = ((c + 1) & 1) * 24576;
            cp_tile16(sb + nb, Abase + (size_t)(c + 1) * 16384, tid);
            cp_tile8(sb + nb + 16384, Wbase + (size_t)(c + 1) * 16384, tid);
            CPA_COMMIT();
            CPA_WAIT1();
        } else {
            CPA_WAIT0();
        }
        __syncthreads();
        uint32_t sa_hi = sb + cur, sa_lo = sb + cur + 8192;
        uint32_t sw_hi = sb + cur + 16384;
#pragma unroll
        for (int ks = 0; ks < 2; ks++) {
            int k = ks * 16;
            uint32_t ah[2][4], al[2][4];
#pragma unroll
            for (int mt = 0; mt < 2; mt++) {
                int row = warp_m * 32 + mt * 16 + lrow + (grp & 1) * 8;
                uint32_t off = swp64(row, (k + (grp >> 1) * 8) * 2);
                ldm4(ah[mt], sa_hi + off);
                ldm4(al[mt], sa_lo + off);
            }
#pragma unroll
            for (int nh = 0; nh < 4; nh++) {
                int krow = k + (lane & 15);
                int ncol = warp_n * 64 + nh * 16 + (lane >> 4) * 8;
                uint32_t offb = swp256(krow, ncol * 2);
                uint32_t bh[4];
                ldm4t(bh, sw_hi + offb);
#pragma unroll
                for (int mt = 0; mt < 2; mt++) {
                    float* c0a = acc[mt * 8 + nh * 2];
                    float* c1a = acc[mt * 8 + nh * 2 + 1];
                    mma_f16(c0a, ah[mt], bh[0], bh[1]);
                    mma_f16(c1a, ah[mt], bh[2], bh[3]);
                    mma_f16(c0a, al[mt], bh[0], bh[1]);
                    mma_f16(c1a, al[mt], bh[2], bh[3]);
                }
            }
        }
        __syncthreads();
    }

    int crow = lane >> 2, cc = (lane & 3) * 2;
    unsigned char* qb = qkvout + (size_t)zz * 32 * 32 * 16384;
#pragma unroll
    for (int mt = 0; mt < 2; mt++) {
#pragma unroll
        for (int t8 = 0; t8 < 8; t8++) {
            const float* c = acc[mt * 8 + t8];
            int n = n0 + warp_n * 64 + t8 * 8 + cc;
            int r0 = m0 + warp_m * 32 + mt * 16 + crow;
            float bb0 = bias[n], bb1 = bias[n + 1];
            if (mode == 2) {
                *(float2*)(fout + (size_t)r0 * E_DIM + n)       = make_float2(c[0] + bb0, c[1] + bb1);
                *(float2*)(fout + (size_t)(r0 + 8) * E_DIM + n) = make_float2(c[2] + bb0, c[3] + bb1);
            } else {
                int h = n >> 6, d = n & 63;
#pragma unroll
                for (int rr = 0; rr < 2; rr++) {
                    int m = r0 + rr * 8;
                    int b = m >> 11, s = m & (S_DIM - 1);
                    int z = b * H_NUM + h;
                    uint32_t lo;
                    uint32_t hi = pack_f16(c[2 * rr] + bb0, c[2 * rr + 1] + bb1, lo);
                    unsigned char* tb = qb + ((size_t)(z * 32 + (s >> 6))) * 16384;
                    uint32_t sw = swp128(s & 63, d * 2);
                    *(uint32_t*)(tb + sw)        = hi;
                    *(uint32_t*)(tb + 8192 + sw) = lo;
                }
            }
        }
    }
}

// ---------------------------------------------------------------------------
// Fused attention, single exp per element.
// Pass 1: 2-term QK ((qh+ql)·kh), p~ = ex2(logit·log2e + mask'), row sums;
//         p~ packed fp16 and stored to per-warp-private gmem blob (frag layout).
// Pass 2: LDG p~ frags; attn = p~·inv (write); PV = p~·vh; ctx scaled by inv.
// 128-j stages double-buffered; mrow2 = mask·(-1.4427e9) in smem.
// ---------------------------------------------------------------------------
#define FA_SMEM (32768 + 8192)
__global__ void __launch_bounds__(256, 2) fused_attn(
    const unsigned char* __restrict__ q2, const unsigned char* __restrict__ k2,
    const unsigned char* __restrict__ v2, const float* __restrict__ mask,
    float* __restrict__ attn, unsigned char* __restrict__ ctx2,
    unsigned char* __restrict__ ptblob)
{
    extern __shared__ char sm[];
    uint32_t sb = smem_u32(sm);
    float* mrow2 = (float*)(sm + 32768);
    int tid = threadIdx.x, lane = tid & 31, wid = tid >> 5;
    int z = blockIdx.y, i0 = blockIdx.x * 128;
    const unsigned char* Kb = k2 + ((size_t)z * 32) * 16384;
    const unsigned char* Vb = v2 + ((size_t)z * 32) * 16384;
    const float* mb = mask + (size_t)(z >> 4) * S_DIM;
    int lrow = lane & 7, grp = lane >> 3;
    int g = lane >> 2, cc = (lane & 3) * 2;
    unsigned char* pt = ptblob + ((size_t)((z * 16 + blockIdx.x) * 8 + wid)) * 65536;
    const float C1 = 0.125f * 1.44269504f;

    for (int t = tid; t < S_DIM; t += 256) mrow2[t] = -1.44269504e9f * mb[t];
    // stage Q (2 tiles hi+lo = 32KB), read frags, release
    {
        const unsigned char* qg = q2 + ((size_t)(z * 32 + (i0 >> 6))) * 16384;
#pragma unroll
        for (int i = 0; i < 8; i++)
            cpa16(sb + tid * 16 + i * 4096, qg + tid * 16 + i * 4096);
        CPA_COMMIT();
        CPA_WAIT0();
    }
    __syncthreads();

    uint32_t qh[4][4], ql[4][4];
#pragma unroll
    for (int t = 0; t < 4; t++) {
        int row = wid * 16 + lrow + (grp & 1) * 8;
        uint32_t off = (uint32_t)(row >> 6) * 16384 + swp128(row & 63, (t * 16 + (grp >> 1) * 8) * 2);
        ldm4(qh[t], sb + off);
        ldm4(ql[t], sb + 8192 + off);
    }
    __syncthreads();

    // ---------------- pass 1: logits -> p~, row sums, store p~ frags ----------------
    float rsum0 = 0.f, rsum1 = 0.f;
    cp_tile8(sb, Kb, tid);
    cp_tile8(sb + 8192, Kb + 16384, tid);
    CPA_COMMIT();
    for (int c = 0; c < 16; c++) {
        int cur = (c & 1) * 16384;
        if (c < 15) {
            int nb = ((c + 1) & 1) * 16384;
            cp_tile8(sb + nb, Kb + (size_t)(2 * c + 2) * 16384, tid);
            cp_tile8(sb + nb + 8192, Kb + (size_t)(2 * c + 3) * 16384, tid);
            CPA_COMMIT();
            CPA_WAIT1();
        } else {
            CPA_WAIT0();
        }
        __syncthreads();
#pragma unroll
        for (int sub = 0; sub < 2; sub++) {
            uint32_t kh_base = sb + cur + sub * 8192;
            float sc[8][4] = {};
#pragma unroll
            for (int t = 0; t < 4; t++) {
#pragma unroll
                for (int nt = 0; nt < 4; nt++) {
                    int rowb = nt * 16 + lrow + ((grp >> 1) & 1) * 8;
                    uint32_t offb = swp128(rowb, (t * 16 + (grp & 1) * 8) * 2);
                    uint32_t bh[4];
                    ldm4(bh, kh_base + offb);
                    float* c0a = sc[nt * 2];
                    float* c1a = sc[nt * 2 + 1];
                    mma_f16(c0a, qh[t], bh[0], bh[1]);
                    mma_f16(c1a, qh[t], bh[2], bh[3]);
                    mma_f16(c0a, ql[t], bh[0], bh[1]);
                    mma_f16(c1a, ql[t], bh[2], bh[3]);
                }
            }
            int jb = c * 128 + sub * 64;
            uint32_t soff = (uint32_t)(c * 2 + sub) * 2048 + lane * 16;
#pragma unroll
            for (int t = 0; t < 4; t++) {
                uint32_t pah[4];
#pragma unroll
                for (int h2 = 0; h2 < 2; h2++) {
                    int t8 = t * 2 + h2;
                    int j = jb + t8 * 8 + cc;
                    float m0 = mrow2[j], m1 = mrow2[j + 1];
                    float p0 = ex2f(fmaf(sc[t8][0], C1, m0));
                    float p1 = ex2f(fmaf(sc[t8][1], C1, m1));
                    float p2 = ex2f(fmaf(sc[t8][2], C1, m0));
                    float p3 = ex2f(fmaf(sc[t8][3], C1, m1));
                    rsum0 += p0 + p1;
                    rsum1 += p2 + p3;
                    pah[h2 * 2]     = pack_f16_hi(p0, p1);
                    pah[h2 * 2 + 1] = pack_f16_hi(p2, p3);
                }
                *(uint4*)(pt + soff + t * 512) = make_uint4(pah[0], pah[1], pah[2], pah[3]);
            }
        }
        __syncthreads();
    }
    rsum0 += __shfl_xor_sync(0xFFFFFFFFu, rsum0, 1);
    rsum0 += __shfl_xor_sync(0xFFFFFFFFu, rsum0, 2);
    rsum1 += __shfl_xor_sync(0xFFFFFFFFu, rsum1, 1);
    rsum1 += __shfl_xor_sync(0xFFFFFFFFu, rsum1, 2);
    float inv0 = 1.0f / rsum0;
    float inv1 = 1.0f / rsum1;

    // ---------------- pass 2: attn = p~·inv, ctx = (p~ @ V_hi)·inv ----------------
    int iRow = i0 + wid * 16 + g;
    float* attn0 = attn + ((size_t)z * S_DIM + iRow) * S_DIM;
    float* attn1 = attn0 + 8 * S_DIM;
    float cacc[8][4] = {};

    cp_tile8(sb, Vb, tid);
    cp_tile8(sb + 8192, Vb + 16384, tid);
    CPA_COMMIT();
    for (int c = 0; c < 16; c++) {
        int cur = (c & 1) * 16384;
        if (c < 15) {
            int nb = ((c + 1) & 1) * 16384;
            cp_tile8(sb + nb,        Vb + (size_t)(2 * c + 2) * 16384, tid);
            cp_tile8(sb + nb + 8192, Vb + (size_t)(2 * c + 3) * 16384, tid);
            CPA_COMMIT();
            CPA_WAIT1();
        } else {
            CPA_WAIT0();
        }
        __syncthreads();
#pragma unroll
        for (int sub = 0; sub < 2; sub++) {
            uint32_t vh_base = sb + cur + sub * 8192;
            int jb = c * 128 + sub * 64;
            uint32_t soff = (uint32_t)(c * 2 + sub) * 2048 + lane * 16;
#pragma unroll
            for (int t = 0; t < 4; t++) {
                uint4 pv = *(const uint4*)(pt + soff + t * 512);
                uint32_t pah[4] = {pv.x, pv.y, pv.z, pv.w};
#pragma unroll
                for (int h2 = 0; h2 < 2; h2++) {
                    int j = jb + (t * 2 + h2) * 8 + cc;
                    float2 f0 = __half22float2(*(__half2*)&pah[h2 * 2]);
                    float2 f1 = __half22float2(*(__half2*)&pah[h2 * 2 + 1]);
                    __stcs((float2*)(attn0 + j), make_float2(f0.x * inv0, f0.y * inv0));
                    __stcs((float2*)(attn1 + j), make_float2(f1.x * inv1, f1.y * inv1));
                }
#pragma unroll
                for (int dt = 0; dt < 4; dt++) {
                    int krow = t * 16 + (lane & 15);
                    int ncol = dt * 16 + (lane >> 4) * 8;
                    uint32_t offb = swp128(krow, ncol * 2);
                    uint32_t vh[4];
                    ldm4t(vh, vh_base + offb);
                    mma_f16(cacc[dt * 2],     pah, vh[0], vh[1]);
                    mma_f16(cacc[dt * 2 + 1], pah, vh[2], vh[3]);
                }
            }
        }
        __syncthreads();
    }

    // ctx epilogue: scale by inv, write tiled fp16 hi/lo for O-proj A operand
    int b = z >> 4, h = z & 15;
    int mb2 = (b * S_DIM + i0) >> 7;
    int r = wid * 16 + g;
#pragma unroll
    for (int t8 = 0; t8 < 8; t8++) {
        int d0 = t8 * 8 + cc;
        int n = h * DH_DIM + d0;
        int kc = n >> 5, col = n & 31;
        unsigned char* base = ctx2 + ((size_t)(mb2 * 32 + kc)) * 16384;
        uint32_t lo0, lo1;
        uint32_t hi0 = pack_f16(cacc[t8][0] * inv0, cacc[t8][1] * inv0, lo0);
        uint32_t hi1 = pack_f16(cacc[t8][2] * inv1, cacc[t8][3] * inv1, lo1);
        uint32_t a0 = swp64(r, col * 2);
        uint32_t a1 = swp64(r + 8, col * 2);
        *(uint32_t*)(base + a0)        = hi0;
        *(uint32_t*)(base + 8192 + a0) = lo0;
        *(uint32_t*)(base + a1)        = hi1;
        *(uint32_t*)(base + 8192 + a1) = lo1;
    }
}

// ---------------------------------------------------------------------------

extern "C" void kernel_launch(void* const* d_in, const int* in_sizes, int n_in,
                              void* d_out, int out_size)
{
    const float* features = (const float*)d_in[0];
    const float* mask     = (const float*)d_in[1];
    const float* Wq = (const float*)d_in[2];
    const float* bq = (const float*)d_in[3];
    const float* Wk = (const float*)d_in[4];
    const float* bk = (const float*)d_in[5];
    const float* Wv = (const float*)d_in[6];
    const float* bv = (const float*)d_in[7];
    const float* Wo = (const float*)d_in[8];
    const float* bo = (const float*)d_in[9];
    float* out = (float*)d_out;

    unsigned char *A2, *W2, *qkv2, *ctx2, *ptb;
    float* attn_scratch;
    cudaGetSymbolAddress((void**)&A2, g_A2);
    cudaGetSymbolAddress((void**)&W2, g_W2);
    cudaGetSymbolAddress((void**)&qkv2, g_qkv2);
    cudaGetSymbolAddress((void**)&ctx2, g_ctx2);
    cudaGetSymbolAddress((void**)&ptb, g_pt);
    cudaGetSymbolAddress((void**)&attn_scratch, g_attn);

    const long long OUT_ELEMS  = (long long)M_ROWS * E_DIM;
    const long long ATTN_ELEMS = (long long)BH_NUM * S_DIM * S_DIM;
    float* attn = ((long long)out_size >= OUT_ELEMS + ATTN_ELEMS)
                      ? (out + OUT_ELEMS) : attn_scratch;

    cudaFuncSetAttribute(proj_mma, cudaFuncAttributeMaxDynamicSharedMemorySize, PROJ_SMEM);
    cudaFuncSetAttribute(fused_attn, cudaFuncAttributeMaxDynamicSharedMemorySize, FA_SMEM);
    cudaFuncSetAttribute(proj_mma, cudaFuncAttributePreferredSharedMemoryCarveout, 100);
    cudaFuncSetAttribute(fused_attn, cudaFuncAttributePreferredSharedMemoryCarveout, 100);

    dim3 blk(256);
    convA<<<dim3(32, 32), blk>>>(features, A2);
    convW<<<dim3(32, 8, 4), blk>>>(Wq, Wk, Wv, Wo, W2);
    proj_mma<<<dim3(8, 32, 3), blk, PROJ_SMEM>>>(A2, W2, bq, bk, bv, qkv2, nullptr, 0);
    fused_attn<<<dim3(16, 32), blk, FA_SMEM>>>(
        qkv2, qkv2 + (size_t)32 * 32 * 16384, qkv2 + (size_t)2 * 32 * 32 * 16384,
        mask, attn, ctx2, ptb);
    proj_mma<<<dim3(8, 32, 1), blk, PROJ_SMEM>>>(
        ctx2, W2 + (size_t)3 * 8 * 32 * 16384, bo, bo, bo, nullptr, out, 2);
}

// round 17
// speedup vs baseline: 1.1723x; 1.1723x over previous
#include <cuda_runtime.h>
#include <cuda_bf16.h>
#include <cuda_fp16.h>
#include <cstdint>
#include <cstddef>

#define S_DIM 2048
#define E_DIM 1024
#define H_NUM 16
#define DH_DIM 64
#define B_NUM 2
#define BH_NUM (B_NUM * H_NUM)     // 32
#define M_ROWS (B_NUM * S_DIM)     // 4096

// tiled fp16 hi/lo operand images (each tile = 8KB hi plane + 8KB lo plane)
__device__ __align__(16) unsigned char g_A2[(size_t)32 * 32 * 16384];        // features tiled [mb][kc]
__device__ __align__(16) unsigned char g_W2[(size_t)4 * 8 * 32 * 16384];     // 4 weights [w][nb][kc]
__device__ __align__(16) unsigned char g_qkv2[(size_t)3 * 32 * 32 * 16384];  // q/k/v [which][z][t]
__device__ __align__(16) unsigned char g_ctx2[(size_t)32 * 32 * 16384];      // ctx tiled [mb][kc]
__device__ float g_attn[(size_t)BH_NUM * S_DIM * S_DIM];                     // fallback

// ---------------------------------------------------------------------------
// helpers
// ---------------------------------------------------------------------------
__device__ __forceinline__ uint32_t smem_u32(const void* p) {
    uint32_t a;
    asm("{ .reg .u64 t; cvta.to.shared.u64 t, %1; cvt.u32.u64 %0, t; }" : "=r"(a) : "l"(p));
    return a;
}
__device__ __forceinline__ void ldm4(uint32_t* r, uint32_t a) {
    asm volatile("ldmatrix.sync.aligned.m8n8.x4.shared.b16 {%0,%1,%2,%3}, [%4];"
        : "=r"(r[0]), "=r"(r[1]), "=r"(r[2]), "=r"(r[3]) : "r"(a));
}
__device__ __forceinline__ void ldm4t(uint32_t* r, uint32_t a) {
    asm volatile("ldmatrix.sync.aligned.m8n8.x4.trans.shared.b16 {%0,%1,%2,%3}, [%4];"
        : "=r"(r[0]), "=r"(r[1]), "=r"(r[2]), "=r"(r[3]) : "r"(a));
}
__device__ __forceinline__ void mma_f16(float* c, const uint32_t* a, uint32_t b0, uint32_t b1) {
    asm volatile(
        "mma.sync.aligned.m16n8k16.row.col.f32.f16.f16.f32 "
        "{%0,%1,%2,%3}, {%4,%5,%6,%7}, {%8,%9}, {%0,%1,%2,%3};"
        : "+f"(c[0]), "+f"(c[1]), "+f"(c[2]), "+f"(c[3])
        : "r"(a[0]), "r"(a[1]), "r"(a[2]), "r"(a[3]), "r"(b0), "r"(b1));
}
__device__ __forceinline__ void cpa16(uint32_t s, const void* g) {
    asm volatile("cp.async.cg.shared.global [%0], [%1], 16;" :: "r"(s), "l"(g));
}
#define CPA_COMMIT() asm volatile("cp.async.commit_group;" ::: "memory")
#define CPA_WAIT0()  asm volatile("cp.async.wait_group 0;" ::: "memory")
#define CPA_WAIT1()  asm volatile("cp.async.wait_group 1;" ::: "memory")

__device__ __forceinline__ uint32_t swp128(int row, int c2) { return (uint32_t)(row * 128 + c2) ^ ((row & 7) << 4); }
__device__ __forceinline__ uint32_t swp64 (int row, int c2) { return (uint32_t)(row * 64  + c2) ^ (((row >> 1) & 3) << 4); }
__device__ __forceinline__ uint32_t swp256(int row, int c2) { return (uint32_t)(row * 256 + c2) ^ ((row & 7) << 4); }

__device__ __forceinline__ float ex2f(float x) {
    float y;
    asm("ex2.approx.f32 %0, %1;" : "=f"(y) : "f"(x));
    return y;
}

// fp16 hi/lo split of 8 floats
__device__ __forceinline__ void split8_f16(const float* v, uint32_t* hi, uint32_t* lo) {
#pragma unroll
    for (int q = 0; q < 4; q++) {
        __half h0 = __float2half_rn(v[2*q]);
        __half h1 = __float2half_rn(v[2*q+1]);
        __half l0 = __float2half_rn(v[2*q]   - __half2float(h0));
        __half l1 = __float2half_rn(v[2*q+1] - __half2float(h1));
        hi[q] = (uint32_t)__half_as_ushort(h0) | ((uint32_t)__half_as_ushort(h1) << 16);
        lo[q] = (uint32_t)__half_as_ushort(l0) | ((uint32_t)__half_as_ushort(l1) << 16);
    }
}
__device__ __forceinline__ uint32_t pack_f16(float a, float b, uint32_t& lo) {
    __half ha = __float2half_rn(a), hb = __float2half_rn(b);
    __half la = __float2half_rn(a - __half2float(ha));
    __half lb = __float2half_rn(b - __half2float(hb));
    lo = (uint32_t)__half_as_ushort(la) | ((uint32_t)__half_as_ushort(lb) << 16);
    return (uint32_t)__half_as_ushort(ha) | ((uint32_t)__half_as_ushort(hb) << 16);
}
__device__ __forceinline__ uint32_t pack_f16_hi(float a, float b) {
    __half ha = __float2half_rn(a), hb = __float2half_rn(b);
    return (uint32_t)__half_as_ushort(ha) | ((uint32_t)__half_as_ushort(hb) << 16);
}
// copy one 16KB tile (hi+lo planes) gmem->smem, 256 threads
__device__ __forceinline__ void cp_tile16(uint32_t sdst, const unsigned char* gsrc, int tid) {
#pragma unroll
    for (int i = 0; i < 4; i++)
        cpa16(sdst + tid * 16 + i * 4096, gsrc + tid * 16 + i * 4096);
}
// copy only the 8KB hi plane, 256 threads
__device__ __forceinline__ void cp_tile8(uint32_t sdst, const unsigned char* gsrc, int tid) {
#pragma unroll
    for (int i = 0; i < 2; i++)
        cpa16(sdst + tid * 16 + i * 4096, gsrc + tid * 16 + i * 4096);
}

// ---------------------------------------------------------------------------
// conversion kernels (run once, cheap) — fp16 hi/lo images
// ---------------------------------------------------------------------------
__global__ void __launch_bounds__(256) convA(const float* __restrict__ src,
                                             unsigned char* __restrict__ dst)
{
    int kc = blockIdx.x, mb = blockIdx.y;
    int tid = threadIdx.x;
    int row = tid >> 1, c0 = (tid & 1) * 16;
    const float* p = src + (size_t)(mb * 128 + row) * E_DIM + kc * 32 + c0;
    unsigned char* base = dst + ((size_t)(mb * 32 + kc)) * 16384;
#pragma unroll
    for (int gi = 0; gi < 2; gi++) {
        float v[8];
        *(float4*)(v)     = *(const float4*)(p + gi * 8);
        *(float4*)(v + 4) = *(const float4*)(p + gi * 8 + 4);
        uint32_t hi[4], lo[4];
        split8_f16(v, hi, lo);
        uint32_t sw = swp64(row, (c0 + gi * 8) * 2);
        *(uint4*)(base + sw)        = make_uint4(hi[0], hi[1], hi[2], hi[3]);
        *(uint4*)(base + 8192 + sw) = make_uint4(lo[0], lo[1], lo[2], lo[3]);
    }
}
__global__ void __launch_bounds__(256) convW(
    const float* __restrict__ Wq, const float* __restrict__ Wk,
    const float* __restrict__ Wv, const float* __restrict__ Wo,
    unsigned char* __restrict__ dst)
{
    int kc = blockIdx.x, nb = blockIdx.y, w = blockIdx.z;
    const float* W = w == 0 ? Wq : (w == 1 ? Wk : (w == 2 ? Wv : Wo));
    int tid = threadIdx.x;
    int krow = tid >> 3, nseg = (tid & 7) * 16;
    const float* p = W + (size_t)(kc * 32 + krow) * E_DIM + nb * 128 + nseg;
    unsigned char* base = dst + ((size_t)w * 8 * 32 + (size_t)(nb * 32 + kc)) * 16384;
#pragma unroll
    for (int gi = 0; gi < 2; gi++) {
        float v[8];
        *(float4*)(v)     = *(const float4*)(p + gi * 8);
        *(float4*)(v + 4) = *(const float4*)(p + gi * 8 + 4);
        uint32_t hi[4], lo[4];
        split8_f16(v, hi, lo);
        uint32_t sw = swp256(krow, (nseg + gi * 8) * 2);
        *(uint4*)(base + sw)        = make_uint4(hi[0], hi[1], hi[2], hi[3]);
        *(uint4*)(base + 8192 + sw) = make_uint4(lo[0], lo[1], lo[2], lo[3]);
    }
}

// ---------------------------------------------------------------------------
// Projection GEMM, fp16 2-term: C = (A_hi + A_lo) @ W_hi + bias.
// Stage = TWO 32-k sub-chunks (48KB), double-buffered (96KB smem) — 16 syncs.
// mode 0: epilogue packs q/k/v as fp16 hi/lo tiles.  mode 2: fp32 out + bias.
// ---------------------------------------------------------------------------
#define PROJ_SMEM 98304
__global__ void __launch_bounds__(256, 2) proj_mma(
    const unsigned char* __restrict__ A2, const unsigned char* __restrict__ W2,
    const float* __restrict__ b0p, const float* __restrict__ b1p, const float* __restrict__ b2p,
    unsigned char* __restrict__ qkvout, float* __restrict__ fout, int mode)
{
    extern __shared__ char sm[];
    uint32_t sb = smem_u32(sm);
    int zz = blockIdx.z;
    const float* bias = zz == 0 ? b0p : (zz == 1 ? b1p : b2p);
    const unsigned char* Wsel = W2 + (size_t)zz * 8 * 32 * 16384;

    int tid = threadIdx.x, lane = tid & 31, wid = tid >> 5;
    int warp_m = wid & 3, warp_n = wid >> 2;
    int n0 = blockIdx.x * 128, m0 = blockIdx.y * 128;
    int lrow = lane & 7, grp = lane >> 3;
    const unsigned char* Abase = A2 + ((size_t)(m0 >> 7) * 32) * 16384;
    const unsigned char* Wbase = Wsel + ((size_t)(n0 >> 7) * 32) * 16384;

    float acc[16][4] = {};
    // prime stage 0: chunks 0,1
    cp_tile16(sb,             Abase, tid);
    cp_tile8 (sb + 16384,     Wbase, tid);
    cp_tile16(sb + 24576,     Abase + 16384, tid);
    cp_tile8 (sb + 40960,     Wbase + 16384, tid);
    CPA_COMMIT();

    for (int c = 0; c < 16; c++) {
        int cur = (c & 1) * 49152;
        if (c < 15) {
            int nb = ((c + 1) & 1) * 49152;
            cp_tile16(sb + nb,         Abase + (size_t)(2 * c + 2) * 16384, tid);
            cp_tile8 (sb + nb + 16384, Wbase + (size_t)(2 * c + 2) * 16384, tid);
            cp_tile16(sb + nb + 24576, Abase + (size_t)(2 * c + 3) * 16384, tid);
            cp_tile8 (sb + nb + 40960, Wbase + (size_t)(2 * c + 3) * 16384, tid);
            CPA_COMMIT();
            CPA_WAIT1();
        } else {
            CPA_WAIT0();
        }
        __syncthreads();
#pragma unroll
        for (int sub = 0; sub < 2; sub++) {
            uint32_t sa_hi = sb + cur + sub * 24576, sa_lo = sa_hi + 8192;
            uint32_t sw_hi = sa_hi + 16384;
#pragma unroll
            for (int ks = 0; ks < 2; ks++) {
                int k = ks * 16;
                uint32_t ah[2][4], al[2][4];
#pragma unroll
                for (int mt = 0; mt < 2; mt++) {
                    int row = warp_m * 32 + mt * 16 + lrow + (grp & 1) * 8;
                    uint32_t off = swp64(row, (k + (grp >> 1) * 8) * 2);
                    ldm4(ah[mt], sa_hi + off);
                    ldm4(al[mt], sa_lo + off);
                }
#pragma unroll
                for (int nh = 0; nh < 4; nh++) {
                    int krow = k + (lane & 15);
                    int ncol = warp_n * 64 + nh * 16 + (lane >> 4) * 8;
                    uint32_t offb = swp256(krow, ncol * 2);
                    uint32_t bh[4];
                    ldm4t(bh, sw_hi + offb);
#pragma unroll
                    for (int mt = 0; mt < 2; mt++) {
                        float* c0a = acc[mt * 8 + nh * 2];
                        float* c1a = acc[mt * 8 + nh * 2 + 1];
                        mma_f16(c0a, ah[mt], bh[0], bh[1]);
                        mma_f16(c1a, ah[mt], bh[2], bh[3]);
                        mma_f16(c0a, al[mt], bh[0], bh[1]);
                        mma_f16(c1a, al[mt], bh[2], bh[3]);
                    }
                }
            }
        }
        __syncthreads();
    }

    int crow = lane >> 2, cc = (lane & 3) * 2;
    unsigned char* qb = qkvout + (size_t)zz * 32 * 32 * 16384;
#pragma unroll
    for (int mt = 0; mt < 2; mt++) {
#pragma unroll
        for (int t8 = 0; t8 < 8; t8++) {
            const float* c = acc[mt * 8 + t8];
            int n = n0 + warp_n * 64 + t8 * 8 + cc;
            int r0 = m0 + warp_m * 32 + mt * 16 + crow;
            float bb0 = bias[n], bb1 = bias[n + 1];
            if (mode == 2) {
                *(float2*)(fout + (size_t)r0 * E_DIM + n)       = make_float2(c[0] + bb0, c[1] + bb1);
                *(float2*)(fout + (size_t)(r0 + 8) * E_DIM + n) = make_float2(c[2] + bb0, c[3] + bb1);
            } else {
                int h = n >> 6, d = n & 63;
#pragma unroll
                for (int rr = 0; rr < 2; rr++) {
                    int m = r0 + rr * 8;
                    int b = m >> 11, s = m & (S_DIM - 1);
                    int z = b * H_NUM + h;
                    uint32_t lo;
                    uint32_t hi = pack_f16(c[2 * rr] + bb0, c[2 * rr + 1] + bb1, lo);
                    unsigned char* tb = qb + ((size_t)(z * 32 + (s >> 6))) * 16384;
                    uint32_t sw = swp128(s & 63, d * 2);
                    *(uint32_t*)(tb + sw)        = hi;
                    *(uint32_t*)(tb + 8192 + sw) = lo;
                }
            }
        }
    }
}

// ---------------------------------------------------------------------------
// Fused attention (R14 structure), fp16 operands, 2 CTAs/SM.
// Pass 1: row sums, 1-term QK (K hi). Pass 2: 2-term QK ((qh+ql)·kh) +
// 1-term PV (p_hi·vh). 128-j stages. ex2 fold; attn via st.global.cs.
// ---------------------------------------------------------------------------
#define FA_SMEM (65536 + 8192)
__global__ void __launch_bounds__(256, 2) fused_attn(
    const unsigned char* __restrict__ q2, const unsigned char* __restrict__ k2,
    const unsigned char* __restrict__ v2, const float* __restrict__ mask,
    float* __restrict__ attn, unsigned char* __restrict__ ctx2)
{
    extern __shared__ char sm[];
    uint32_t sb = smem_u32(sm);
    float* mrow2 = (float*)(sm + 65536);
    int tid = threadIdx.x, lane = tid & 31, wid = tid >> 5;
    int z = blockIdx.y, i0 = blockIdx.x * 128;
    const unsigned char* Kb = k2 + ((size_t)z * 32) * 16384;
    const unsigned char* Vb = v2 + ((size_t)z * 32) * 16384;
    const float* mb = mask + (size_t)(z >> 4) * S_DIM;
    int lrow = lane & 7, grp = lane >> 3;
    int g = lane >> 2, cc = (lane & 3) * 2;
    const float C1 = 0.125f * 1.44269504f;

    for (int t = tid; t < S_DIM; t += 256) mrow2[t] = -1.44269504e9f * mb[t];
    {
        const unsigned char* qg = q2 + ((size_t)(z * 32 + (i0 >> 6))) * 16384;
#pragma unroll
        for (int i = 0; i < 8; i++)
            cpa16(sb + tid * 16 + i * 4096, qg + tid * 16 + i * 4096);
        CPA_COMMIT();
        CPA_WAIT0();
    }
    __syncthreads();

    uint32_t qh[4][4], ql[4][4];
#pragma unroll
    for (int t = 0; t < 4; t++) {
        int row = wid * 16 + lrow + (grp & 1) * 8;
        uint32_t off = (uint32_t)(row >> 6) * 16384 + swp128(row & 63, (t * 16 + (grp >> 1) * 8) * 2);
        ldm4(qh[t], sb + off);
        ldm4(ql[t], sb + 8192 + off);
    }
    __syncthreads();

    // ---------------- pass 1: row sums (K hi, 1-term QK, 128-j stages) ----------------
    float rsum0 = 0.f, rsum1 = 0.f;
    cp_tile8(sb, Kb, tid);
    cp_tile8(sb + 8192, Kb + 16384, tid);
    CPA_COMMIT();
    for (int c = 0; c < 16; c++) {
        int cur = (c & 1) * 16384;
        if (c < 15) {
            int nb = ((c + 1) & 1) * 16384;
            cp_tile8(sb + nb, Kb + (size_t)(2 * c + 2) * 16384, tid);
            cp_tile8(sb + nb + 8192, Kb + (size_t)(2 * c + 3) * 16384, tid);
            CPA_COMMIT();
            CPA_WAIT1();
        } else {
            CPA_WAIT0();
        }
        __syncthreads();
#pragma unroll
        for (int sub = 0; sub < 2; sub++) {
            uint32_t kh_base = sb + cur + sub * 8192;
            float sc[8][4] = {};
#pragma unroll
            for (int t = 0; t < 4; t++) {
#pragma unroll
                for (int nt = 0; nt < 4; nt++) {
                    int rowb = nt * 16 + lrow + ((grp >> 1) & 1) * 8;
                    uint32_t offb = swp128(rowb, (t * 16 + (grp & 1) * 8) * 2);
                    uint32_t bh[4];
                    ldm4(bh, kh_base + offb);
                    mma_f16(sc[nt * 2],     qh[t], bh[0], bh[1]);
                    mma_f16(sc[nt * 2 + 1], qh[t], bh[2], bh[3]);
                }
            }
            int jb = c * 128 + sub * 64;
#pragma unroll
            for (int t8 = 0; t8 < 8; t8++) {
                int j = jb + t8 * 8 + cc;
                float m0 = mrow2[j], m1 = mrow2[j + 1];
                rsum0 += ex2f(fmaf(sc[t8][0], C1, m0)) + ex2f(fmaf(sc[t8][1], C1, m1));
                rsum1 += ex2f(fmaf(sc[t8][2], C1, m0)) + ex2f(fmaf(sc[t8][3], C1, m1));
            }
        }
        __syncthreads();
    }
    rsum0 += __shfl_xor_sync(0xFFFFFFFFu, rsum0, 1);
    rsum0 += __shfl_xor_sync(0xFFFFFFFFu, rsum0, 2);
    rsum1 += __shfl_xor_sync(0xFFFFFFFFu, rsum1, 1);
    rsum1 += __shfl_xor_sync(0xFFFFFFFFu, rsum1, 2);
    float inv0 = 1.0f / rsum0;
    float inv1 = 1.0f / rsum1;

    // ---------------- pass 2: attn + ctx (128-j stages: K hi + V hi) ----------------
    int iRow = i0 + wid * 16 + g;
    float* attn0 = attn + ((size_t)z * S_DIM + iRow) * S_DIM;
    float* attn1 = attn0 + 8 * S_DIM;
    float cacc[8][4] = {};

    cp_tile8(sb, Kb, tid);
    cp_tile8(sb + 8192, Kb + 16384, tid);
    cp_tile8(sb + 16384, Vb, tid);
    cp_tile8(sb + 24576, Vb + 16384, tid);
    CPA_COMMIT();
    for (int c = 0; c < 16; c++) {
        int cur = (c & 1) * 32768;
        if (c < 15) {
            int nb = ((c + 1) & 1) * 32768;
            cp_tile8(sb + nb,         Kb + (size_t)(2 * c + 2) * 16384, tid);
            cp_tile8(sb + nb + 8192,  Kb + (size_t)(2 * c + 3) * 16384, tid);
            cp_tile8(sb + nb + 16384, Vb + (size_t)(2 * c + 2) * 16384, tid);
            cp_tile8(sb + nb + 24576, Vb + (size_t)(2 * c + 3) * 16384, tid);
            CPA_COMMIT();
            CPA_WAIT1();
        } else {
            CPA_WAIT0();
        }
        __syncthreads();
#pragma unroll
        for (int sub = 0; sub < 2; sub++) {
            uint32_t kh_base = sb + cur + sub * 8192;
            uint32_t vh_base = sb + cur + 16384 + sub * 8192;
            float sc[8][4] = {};
#pragma unroll
            for (int t = 0; t < 4; t++) {
#pragma unroll
                for (int nt = 0; nt < 4; nt++) {
                    int rowb = nt * 16 + lrow + ((grp >> 1) & 1) * 8;
                    uint32_t offb = swp128(rowb, (t * 16 + (grp & 1) * 8) * 2);
                    uint32_t bh[4];
                    ldm4(bh, kh_base + offb);
                    float* c0a = sc[nt * 2];
                    float* c1a = sc[nt * 2 + 1];
                    mma_f16(c0a, qh[t], bh[0], bh[1]);
                    mma_f16(c1a, qh[t], bh[2], bh[3]);
                    mma_f16(c0a, ql[t], bh[0], bh[1]);
                    mma_f16(c1a, ql[t], bh[2], bh[3]);
                }
            }
            // per k16-step: exp/normalize/write/pack then 1-term PV
            int jb = c * 128 + sub * 64;
#pragma unroll
            for (int t = 0; t < 4; t++) {
                uint32_t pah[4];
#pragma unroll
                for (int h2 = 0; h2 < 2; h2++) {
                    int t8 = t * 2 + h2;
                    int j = jb + t8 * 8 + cc;
                    float m0 = mrow2[j], m1 = mrow2[j + 1];
                    float p0 = ex2f(fmaf(sc[t8][0], C1, m0)) * inv0;
                    float p1 = ex2f(fmaf(sc[t8][1], C1, m1)) * inv0;
                    float p2 = ex2f(fmaf(sc[t8][2], C1, m0)) * inv1;
                    float p3 = ex2f(fmaf(sc[t8][3], C1, m1)) * inv1;
                    __stcs((float2*)(attn0 + j), make_float2(p0, p1));
                    __stcs((float2*)(attn1 + j), make_float2(p2, p3));
                    pah[h2 * 2]     = pack_f16_hi(p0, p1);
                    pah[h2 * 2 + 1] = pack_f16_hi(p2, p3);
                }
#pragma unroll
                for (int dt = 0; dt < 4; dt++) {
                    int krow = t * 16 + (lane & 15);
                    int ncol = dt * 16 + (lane >> 4) * 8;
                    uint32_t offb = swp128(krow, ncol * 2);
                    uint32_t vh[4];
                    ldm4t(vh, vh_base + offb);
                    mma_f16(cacc[dt * 2],     pah, vh[0], vh[1]);
                    mma_f16(cacc[dt * 2 + 1], pah, vh[2], vh[3]);
                }
            }
        }
        __syncthreads();
    }

    // ctx epilogue: write tiled fp16 hi/lo for O-proj A operand
    int b = z >> 4, h = z & 15;
    int mb2 = (b * S_DIM + i0) >> 7;
    int r = wid * 16 + g;
#pragma unroll
    for (int t8 = 0; t8 < 8; t8++) {
        int d0 = t8 * 8 + cc;
        int n = h * DH_DIM + d0;
        int kc = n >> 5, col = n & 31;
        unsigned char* base = ctx2 + ((size_t)(mb2 * 32 + kc)) * 16384;
        uint32_t lo0, lo1;
        uint32_t hi0 = pack_f16(cacc[t8][0], cacc[t8][1], lo0);
        uint32_t hi1 = pack_f16(cacc[t8][2], cacc[t8][3], lo1);
        uint32_t a0 = swp64(r, col * 2);
        uint32_t a1 = swp64(r + 8, col * 2);
        *(uint32_t*)(base + a0)        = hi0;
        *(uint32_t*)(base + 8192 + a0) = lo0;
        *(uint32_t*)(base + a1)        = hi1;
        *(uint32_t*)(base + 8192 + a1) = lo1;
    }
}

// ---------------------------------------------------------------------------

extern "C" void kernel_launch(void* const* d_in, const int* in_sizes, int n_in,
                              void* d_out, int out_size)
{
    const float* features = (const float*)d_in[0];
    const float* mask     = (const float*)d_in[1];
    const float* Wq = (const float*)d_in[2];
    const float* bq = (const float*)d_in[3];
    const float* Wk = (const float*)d_in[4];
    const float* bk = (const float*)d_in[5];
    const float* Wv = (const float*)d_in[6];
    const float* bv = (const float*)d_in[7];
    const float* Wo = (const float*)d_in[8];
    const float* bo = (const float*)d_in[9];
    float* out = (float*)d_out;

    unsigned char *A2, *W2, *qkv2, *ctx2;
    float* attn_scratch;
    cudaGetSymbolAddress((void**)&A2, g_A2);
    cudaGetSymbolAddress((void**)&W2, g_W2);
    cudaGetSymbolAddress((void**)&qkv2, g_qkv2);
    cudaGetSymbolAddress((void**)&ctx2, g_ctx2);
    cudaGetSymbolAddress((void**)&attn_scratch, g_attn);

    const long long OUT_ELEMS  = (long long)M_ROWS * E_DIM;
    const long long ATTN_ELEMS = (long long)BH_NUM * S_DIM * S_DIM;
    float* attn = ((long long)out_size >= OUT_ELEMS + ATTN_ELEMS)
                      ? (out + OUT_ELEMS) : attn_scratch;

    cudaFuncSetAttribute(proj_mma, cudaFuncAttributeMaxDynamicSharedMemorySize, PROJ_SMEM);
    cudaFuncSetAttribute(fused_attn, cudaFuncAttributeMaxDynamicSharedMemorySize, FA_SMEM);
    cudaFuncSetAttribute(proj_mma, cudaFuncAttributePreferredSharedMemoryCarveout, 100);
    cudaFuncSetAttribute(fused_attn, cudaFuncAttributePreferredSharedMemoryCarveout, 100);

    dim3 blk(256);
    convA<<<dim3(32, 32), blk>>>(features, A2);
    convW<<<dim3(32, 8, 4), blk>>>(Wq, Wk, Wv, Wo, W2);
    proj_mma<<<dim3(8, 32, 3), blk, PROJ_SMEM>>>(A2, W2, bq, bk, bv, qkv2, nullptr, 0);
    fused_attn<<<dim3(16, 32), blk, FA_SMEM>>>(
        qkv2, qkv2 + (size_t)32 * 32 * 16384, qkv2 + (size_t)2 * 32 * 32 * 16384,
        mask, attn, ctx2);
    proj_mma<<<dim3(8, 32, 1), blk, PROJ_SMEM>>>(
        ctx2, W2 + (size_t)3 * 8 * 32 * 16384, bo, bo, bo, nullptr, out, 2);
}